// round 13
// baseline (speedup 1.0000x reference)
#include <cuda_runtime.h>
#include <cuda_bf16.h>
#include <math.h>

// BFP quant-dequant: [8192, 12284] fp32, BLOCK_SIZE=8, 8-bit shared exponent.
// step = 2^(frexp_exp(maxabs) - 7); out = clip(rint(x/step), -128, 127) * step.
//
// 2 BFP blocks per thread (16 floats, 4x LDG.128 front-batched for MLP=4)
// + streaming cache hints (__ldcs/__stcs, evict-first) since all data is
// single-touch. Warp covers 2048 contiguous bytes -> fully coalesced.
//
// Per row: 12284 floats = 3071 float4s (0..3070) = 1536 BFP blocks, block 1535
// partial (4 real elems). Thread pair-index t2 (0..767) handles blocks 2*t2,
// 2*t2+1 = float4s 4*t2 .. 4*t2+3. t2==767: float4 3071 doesn't exist -> the
// second half of block 1535 is implicit zeros (no effect on max, not stored).

#define ROWS   8192
#define COLS   12284
#define PAIRS  768     // pairs of BFP blocks per row
#define LASTP  767     // pair whose 4th float4 is out of range

__device__ __forceinline__ float4 qd4(float4 v, float inv, float step) {
    return make_float4(
        fminf(fmaxf(rintf(v.x * inv), -128.0f), 127.0f) * step,
        fminf(fmaxf(rintf(v.y * inv), -128.0f), 127.0f) * step,
        fminf(fmaxf(rintf(v.z * inv), -128.0f), 127.0f) * step,
        fminf(fmaxf(rintf(v.w * inv), -128.0f), 127.0f) * step);
}

__device__ __forceinline__ float max8(float4 a, float4 b) {
    return fmaxf(fmaxf(fmaxf(fabsf(a.x), fabsf(a.y)), fmaxf(fabsf(a.z), fabsf(a.w))),
                 fmaxf(fmaxf(fabsf(b.x), fabsf(b.y)), fmaxf(fabsf(b.z), fabsf(b.w))));
}

// maxabs = mant * 2^E, mant in [0.5,1) => E = raw_exp - 126.
// step = 2^(E-7) -> bits (raw-6)<<23 ; inv = 2^(7-E) -> bits (260-raw)<<23.
__device__ __forceinline__ void exp_from_max(float m, float& step, float& inv) {
    const unsigned raw = __float_as_uint(m) >> 23;   // m >= 0
    if (raw >= 7u && raw <= 254u) {
        step = __uint_as_float((raw -   6u) << 23);
        inv  = __uint_as_float((260u - raw) << 23);
    } else if (m == 0.0f) {
        step = 0.0f; inv = 0.0f;
    } else {                                          // subnormal maxabs
        int e; (void)frexpf(m, &e);
        step = ldexpf(1.0f, e - 7);
        inv  = ldexpf(1.0f, 7 - e);
    }
}

__global__ __launch_bounds__(256, 6)
void bfp_qdq_kernel(const float* __restrict__ x, float* __restrict__ out)
{
    const int t2 = blockIdx.x * 256 + threadIdx.x;      // pair index in row, 0..767
    const long long rowoff = (long long)blockIdx.y * COLS;
    const float4* __restrict__ src = reinterpret_cast<const float4*>(x + rowoff);
    float4*       __restrict__ dst = reinterpret_cast<float4*>(out + rowoff);

    const int f = 4 * t2;                               // first float4 index
    const bool last = (t2 == LASTP);                    // float4 f+3 out of range

    // Front-batched streaming loads (MLP=4, minus one for the tail thread).
    float4 v0 = __ldcs(src + f + 0);
    float4 v1 = __ldcs(src + f + 1);
    float4 v2 = __ldcs(src + f + 2);
    float4 v3 = last ? make_float4(0.f, 0.f, 0.f, 0.f) : __ldcs(src + f + 3);

    float s0, i0, s1, i1;
    exp_from_max(max8(v0, v1), s0, i0);                 // block 2*t2 (always full)
    exp_from_max(max8(v2, v3), s1, i1);                 // block 2*t2+1 (partial at tail)

    __stcs(dst + f + 0, qd4(v0, i0, s0));
    __stcs(dst + f + 1, qd4(v1, i0, s0));
    __stcs(dst + f + 2, qd4(v2, i1, s1));
    if (!last) __stcs(dst + f + 3, qd4(v3, i1, s1));
}

extern "C" void kernel_launch(void* const* d_in, const int* in_sizes, int n_in,
                              void* d_out, int out_size)
{
    const float* x = (const float*)d_in[0];
    float* out = (float*)d_out;
    dim3 grid(PAIRS / 256, ROWS, 1);   // (3, 8192) -> 24576 CTAs
    bfp_qdq_kernel<<<grid, 256>>>(x, out);
}